// round 4
// baseline (speedup 1.0000x reference)
#include <cuda_runtime.h>
#include <cuda_bf16.h>
#include <cuda_pipeline.h>

#define NUM_CLASSES 1024
#define FEAT_DIM    512
#define BATCH       16384
#define ALPHA       0.5f
#define MAXC        192   // cap on tracked samples/class (Poisson(16): max ~40)
#define DEPTH       3     // cp.async ring depth per warp

// Scratch (allocation-free rule): zero-init at module load; cl_combine re-zeros
// g_cnt each call so graph replays are self-consistent.
__device__ int    g_cnt[NUM_CLASSES];
__device__ int    g_slot[NUM_CLASSES * MAXC];
__device__ float4 g_part[2 * NUM_CLASSES * 128];   // per-(class,half) partial deltas, 4MB

// Kernel 1: histogram + scatter sample indices into per-class slots.
__global__ void cl_hist_scatter(const int* __restrict__ labels) {
    int i = blockIdx.x * blockDim.x + threadIdx.x;
    if (i < BATCH) {
        int c = labels[i];
        int p = atomicAdd(&g_cnt[c], 1);
        if (p < MAXC) g_slot[c * MAXC + p] = i;
    }
}

// Kernel 2: 2 blocks per class (parity-interleaved samples), 4 warps/block.
// Each warp owns whole samples; feature rows are staged gmem->smem with a
// depth-3 cp.async ring (12 LDGSTS in flight/warp, no data registers), slot
// indices are prefetched once and shuffled, per-sample reduce is warp-local.
// Block writes its partial delta to g_part; cl_combine finishes the update.
__global__ __launch_bounds__(128, 8) void cl_main(
    const float4* __restrict__ feat,     // [BATCH][128] float4
    const float4* __restrict__ centers,  // [C][128] float4
    float*        __restrict__ result)   // [BATCH]
{
    const int c    = blockIdx.x >> 1;     // class
    const int h    = blockIdx.x & 1;      // half (sample parity)
    const int t    = threadIdx.x;
    const int lane = t & 31;
    const int w    = t >> 5;

    __shared__ float4 stage[4][DEPTH][128];   // 24KB: per-warp rings

    const int cnt = g_cnt[c];
    const int n   = cnt < MAXC ? cnt : MAXC;

    // samples for this block: j = h + 2m; this warp: m = w + 4k -> j = h+2w+8k
    const int nb   = (n + 1 - h) / 2;                       // block's sample count
    const int nws  = nb > w ? (nb - w + 3) >> 2 : 0;        // this warp's count
    const int base = h + 2 * w;                             // first j for warp

    // Prefetch all slot indices for this warp: lane k holds sample k's index.
    const int* slot  = g_slot + c * MAXC;
    int        myidx = (lane < nws) ? slot[base + 8 * lane] : 0;

    // Per-lane center chunk (float4s lane, lane+32, lane+64, lane+96).
    const float4* crow = centers + c * 128;
    float4 ctr[4];
    #pragma unroll
    for (int k = 0; k < 4; k++) ctr[k] = crow[lane + 32 * k];

    float4 dl[4];
    #pragma unroll
    for (int k = 0; k < 4; k++) dl[k] = make_float4(0.f, 0.f, 0.f, 0.f);

    // Prologue: fill the ring (always commit DEPTH groups, empty ones at tail).
    #pragma unroll
    for (int s = 0; s < DEPTH; s++) {
        if (s < nws) {
            int b = __shfl_sync(0xffffffffu, myidx, s);
            const float4* frow = feat + (size_t)b * 128;
            #pragma unroll
            for (int q = 0; q < 4; q++)
                __pipeline_memcpy_async(&stage[w][s][lane + 32 * q],
                                        &frow[lane + 32 * q], 16);
        }
        __pipeline_commit();
    }

    for (int i = 0; i < nws; i++) {
        __pipeline_wait_prior(DEPTH - 1);          // group i complete

        const int   st = i % DEPTH;
        const int   b  = __shfl_sync(0xffffffffu, myidx, i);
        float4 f[4];
        #pragma unroll
        for (int q = 0; q < 4; q++) f[q] = stage[w][st][lane + 32 * q];

        // Refill this stage with sample i+DEPTH (or an empty group).
        if (i + DEPTH < nws) {
            int bn = __shfl_sync(0xffffffffu, myidx, i + DEPTH);
            const float4* frow = feat + (size_t)bn * 128;
            #pragma unroll
            for (int q = 0; q < 4; q++)
                __pipeline_memcpy_async(&stage[w][st][lane + 32 * q],
                                        &frow[lane + 32 * q], 16);
        }
        __pipeline_commit();

        float ss = 0.f;
        #pragma unroll
        for (int q = 0; q < 4; q++) {
            float4 d;
            d.x = ctr[q].x - f[q].x;
            d.y = ctr[q].y - f[q].y;
            d.z = ctr[q].z - f[q].z;
            d.w = ctr[q].w - f[q].w;
            dl[q].x += d.x; dl[q].y += d.y; dl[q].z += d.z; dl[q].w += d.w;
            ss += d.x * d.x + d.y * d.y + d.z * d.z + d.w * d.w;
        }
        #pragma unroll
        for (int o = 16; o; o >>= 1)
            ss += __shfl_xor_sync(0xffffffffu, ss, o);
        if (lane == 0) result[b] = ss;
    }
    __pipeline_wait_prior(0);   // drain before reusing stage memory

    // Cross-warp delta combine via each warp's own (now idle) stage 0.
    #pragma unroll
    for (int k = 0; k < 4; k++) stage[w][0][lane + 32 * k] = dl[k];
    __syncthreads();

    float4 dsum = stage[0][0][t];
    #pragma unroll
    for (int ww = 1; ww < 4; ww++) {
        float4 v = stage[ww][0][t];
        dsum.x += v.x; dsum.y += v.y; dsum.z += v.z; dsum.w += v.w;
    }
    g_part[blockIdx.x * 128 + t] = dsum;
}

// Kernel 3: combine the two partial deltas per class, write new centers,
// re-zero g_cnt for the next replay.
__global__ __launch_bounds__(128) void cl_combine(
    const float4* __restrict__ centers,
    float4*       __restrict__ newc)
{
    const int c = blockIdx.x;
    const int t = threadIdx.x;

    float4 p0 = g_part[(2 * c)     * 128 + t];
    float4 p1 = g_part[(2 * c + 1) * 128 + t];
    float4 cc = centers[c * 128 + t];

    const float s = ALPHA / (float)(g_cnt[c] + 1);
    float4 nc;
    nc.x = cc.x - (p0.x + p1.x) * s;
    nc.y = cc.y - (p0.y + p1.y) * s;
    nc.z = cc.z - (p0.z + p1.z) * s;
    nc.w = cc.w - (p0.w + p1.w) * s;
    newc[c * 128 + t] = nc;

    if (t == 0) g_cnt[c] = 0;
}

extern "C" void kernel_launch(void* const* d_in, const int* in_sizes, int n_in,
                              void* d_out, int out_size) {
    const float* features = (const float*)d_in[0];   // 16384*512
    const float* centers  = (const float*)d_in[1];   // 1024*512
    const int*   labels   = (const int*)  d_in[2];   // 16384

    float* out        = (float*)d_out;
    float* result     = out;            // [16384]
    float* newcenters = out + BATCH;    // [1024*512], 64KB offset -> 16B aligned

    cl_hist_scatter<<<BATCH / 256, 256>>>(labels);

    cl_main<<<2 * NUM_CLASSES, 128>>>(
        (const float4*)features,
        (const float4*)centers,
        result);

    cl_combine<<<NUM_CLASSES, 128>>>(
        (const float4*)centers,
        (float4*)newcenters);
}